// round 15
// baseline (speedup 1.0000x reference)
#include <cuda_runtime.h>
#include <cuda_fp16.h>
#include <stdint.h>

#define BATCH 8
#define SEQ   2048
#define EMB   1024
#define HD    128

// fp16 weights (converted once); X is consumed fp32 directly by proj
__device__ half g_w[3 * HD * EMB];        // Wq|Wk|Wv
// fp16 scratch for q,k,v
__device__ half g_q[BATCH * SEQ * HD];
__device__ half g_k[BATCH * SEQ * HD];
__device__ half g_v[BATCH * SEQ * HD];

// ---------------------------------------------------------------- helpers
__device__ __forceinline__ uint32_t smem_u32(const void* p) {
    uint32_t a;
    asm("{ .reg .u64 t; cvta.to.shared.u64 t, %1; cvt.u32.u64 %0, t; }"
        : "=r"(a) : "l"(p));
    return a;
}
__device__ __forceinline__ void ldsm_x4(uint32_t& r0, uint32_t& r1, uint32_t& r2,
                                        uint32_t& r3, uint32_t addr) {
    asm volatile("ldmatrix.sync.aligned.m8n8.x4.shared.b16 {%0,%1,%2,%3}, [%4];"
                 : "=r"(r0), "=r"(r1), "=r"(r2), "=r"(r3) : "r"(addr));
}
__device__ __forceinline__ void ldsm_x4_t(uint32_t& r0, uint32_t& r1, uint32_t& r2,
                                          uint32_t& r3, uint32_t addr) {
    asm volatile("ldmatrix.sync.aligned.m8n8.x4.trans.shared.b16 {%0,%1,%2,%3}, [%4];"
                 : "=r"(r0), "=r"(r1), "=r"(r2), "=r"(r3) : "r"(addr));
}
__device__ __forceinline__ void mma16816(float* c, uint32_t a0, uint32_t a1,
                                         uint32_t a2, uint32_t a3,
                                         uint32_t b0, uint32_t b1) {
    asm volatile(
        "mma.sync.aligned.m16n8k16.row.col.f32.f16.f16.f32 "
        "{%0,%1,%2,%3},{%4,%5,%6,%7},{%8,%9},{%0,%1,%2,%3};"
        : "+f"(c[0]), "+f"(c[1]), "+f"(c[2]), "+f"(c[3])
        : "r"(a0), "r"(a1), "r"(a2), "r"(a3), "r"(b0), "r"(b1));
}
__device__ __forceinline__ uint32_t pack_h2(float lo, float hi) {
    uint32_t r;
    asm("cvt.rn.f16x2.f32 %0, %1, %2;" : "=r"(r) : "f"(hi), "f"(lo));
    return r;
}
__device__ __forceinline__ uint32_t h2exp2(uint32_t x) {
    uint32_t r;
    asm("ex2.approx.f16x2 %0, %1;" : "=r"(r) : "r"(x));
    return r;
}
__device__ __forceinline__ void cp16(uint32_t dst, const void* src) {
    asm volatile("cp.async.cg.shared.global [%0], [%1], 16;"
                 :: "r"(dst), "l"(src));
}
__device__ __forceinline__ void cp_commit() {
    asm volatile("cp.async.commit_group;");
}
template <int N>
__device__ __forceinline__ void cp_wait() {
    asm volatile("cp.async.wait_group %0;" :: "n"(N));
}

// ---------------------------------------------------------------- converter
// W only: 3 * 128 * 1024 floats -> fp16.
__global__ __launch_bounds__(256)
void cvt_w_kernel(const float* __restrict__ Wq,
                  const float* __restrict__ Wk,
                  const float* __restrict__ Wv)
{
    size_t i4 = (size_t)blockIdx.x * 256 + threadIdx.x;
    size_t j  = i4 * 4;
    const float* src = (j < 131072) ? Wq : (j < 262144) ? Wk : Wv;
    size_t off = j & 131071;
    float4 v = *(const float4*)(src + off);
    *(uint2*)&g_w[j] = make_uint2(pack_h2(v.x, v.y), pack_h2(v.z, v.w));
}

// ---------------------------------------------------------------- projection
// out[m][n] = sum_k X[m][k]*W[n][k]. A: fp32 LDG inside the iteration,
// converted in-register -> fp16 STS (short live range, no spill). B: fp16
// cp.async 3-stage. ONE __syncthreads per stage. 128x128 CTA, 8 warps.
#define PP 72                       // halves per row (36 words = 4 mod 32)
#define PSTG (128 * PP)             // halves per stage buffer
#define PSTGB (PSTG * 2)            // bytes per stage
#define PROJ_SMEM (6 * PSTGB)       // A0 A1 A2 B0 B1 B2 (~110KB -> 2 CTA/SM)

__global__ __launch_bounds__(256, 2)
void proj_kernel(const float* __restrict__ X)
{
    extern __shared__ half psm[];
    const uint32_t aBase = smem_u32(psm);
    const uint32_t bBase = aBase + 3 * PSTGB;

    half* outp = (blockIdx.y == 0) ? g_q : (blockIdx.y == 1) ? g_k : g_v;
    const float* Ab = X + (size_t)blockIdx.x * 128 * EMB;
    const half*  Bb = g_w + (size_t)blockIdx.y * HD * EMB;

    const int tid  = threadIdx.x;
    const int lane = tid & 31;
    const int w    = tid >> 5;
    const int wm   = w >> 2;
    const int wn   = w & 3;
    const int l15  = lane & 15;
    const int g    = lane >> 2;
    const int t0   = lane & 3;

    float acc[4][4][4];
    #pragma unroll
    for (int i = 0; i < 4; i++)
        #pragma unroll
        for (int j = 0; j < 4; j++)
            #pragma unroll
            for (int r = 0; r < 4; r++) acc[i][j][r] = 0.f;

    uint32_t offA[4], offB[2];
    #pragma unroll
    for (int mb = 0; mb < 4; mb++)
        offA[mb] = (((wm * 64 + mb * 16 + l15) * PP) + (lane >> 4) * 8) * 2;
    #pragma unroll
    for (int nbp = 0; nbp < 2; nbp++)
        offB[nbp] = (((wn * 32 + nbp * 16 + (l15 & 7) + (lane >> 4) * 8) * PP)
                     + ((lane >> 3) & 1) * 8) * 2;

    const int ld_row = tid >> 3;    // 0..31; rows ld_row + 32*i
    const int ld_c   = tid & 7;     // 8-float chunks

    auto load_B = [&](int st, int t) {
        const int kt = t * 64;
        #pragma unroll
        for (int i = 0; i < 4; i++) {
            int p = tid + 256 * i, row = p >> 3, c = p & 7;
            cp16(bBase + st * PSTGB + (row * PP + c * 8) * 2,
                 Bb + (size_t)row * EMB + kt + c * 8);
        }
    };

    load_B(0, 0); cp_commit();
    load_B(1, 1); cp_commit();

    for (int t = 0; t < 16; t++) {
        const int cur = t % 3;

        // A stage t: LDG fp32 -> cvt -> STS fp16 into slot cur.
        // Slot cur last read at iter t-3 (warps passed barriers t-2, t-1),
        // so the write is race-free with ONE barrier per iteration.
        {
            const int kt = t * 64;
            #pragma unroll
            for (int i = 0; i < 4; i++) {
                const float* src = Ab + (size_t)(ld_row + 32 * i) * EMB + kt + ld_c * 8;
                float4 rx = *(const float4*)src;
                float4 ry = *(const float4*)(src + 4);
                uint32_t addr = aBase + cur * PSTGB
                              + (((ld_row + 32 * i) * PP) + ld_c * 8) * 2;
                uint32_t v0 = pack_h2(rx.x, rx.y);
                uint32_t v1 = pack_h2(rx.z, rx.w);
                uint32_t v2 = pack_h2(ry.x, ry.y);
                uint32_t v3 = pack_h2(ry.z, ry.w);
                asm volatile("st.shared.v4.b32 [%0], {%1,%2,%3,%4};"
                             :: "r"(addr), "r"(v0), "r"(v1), "r"(v2), "r"(v3));
            }
        }
        cp_wait<1>();              // B stage t landed (t+1 may be in flight)
        __syncthreads();           // STS + cp.async visible to all warps

        const uint32_t aB = aBase + cur * PSTGB;
        const uint32_t bB = bBase + cur * PSTGB;
        #pragma unroll
        for (int ks = 0; ks < 4; ks++) {
            uint32_t a[4][4];
            #pragma unroll
            for (int mb = 0; mb < 4; mb++)
                ldsm_x4(a[mb][0], a[mb][1], a[mb][2], a[mb][3],
                        aB + offA[mb] + ks * 32);
            #pragma unroll
            for (int nbp = 0; nbp < 2; nbp++) {
                uint32_t b0, b1, b2, b3;
                ldsm_x4(b0, b1, b2, b3, bB + offB[nbp] + ks * 32);
                #pragma unroll
                for (int mb = 0; mb < 4; mb++) {
                    mma16816(acc[mb][2 * nbp],     a[mb][0], a[mb][1], a[mb][2], a[mb][3], b0, b1);
                    mma16816(acc[mb][2 * nbp + 1], a[mb][0], a[mb][1], a[mb][2], a[mb][3], b2, b3);
                }
            }
        }
        if (t + 2 < 16) load_B((t + 2) % 3, t + 2);
        cp_commit();
    }

    // epilogue: q gets the softmax scale folded in (log2(e)/128)
    const float qs = (blockIdx.y == 0) ? 0.011271055007086637f : 1.0f;
    const int m0 = blockIdx.x * 128;
    #pragma unroll
    for (int mb = 0; mb < 4; mb++)
        #pragma unroll
        for (int nb = 0; nb < 4; nb++) {
            int row = m0 + wm * 64 + mb * 16 + g;
            int col = wn * 32 + nb * 8 + 2 * t0;
            *(uint32_t*)&outp[(size_t)row * HD + col] =
                pack_h2(acc[mb][nb][0] * qs, acc[mb][nb][1] * qs);
            *(uint32_t*)&outp[(size_t)(row + 8) * HD + col] =
                pack_h2(acc[mb][nb][2] * qs, acc[mb][nb][3] * qs);
        }
}

// ---------------------------------------------------------------- attention
// R12 attention (verbatim, best known): BR=64, BC=128, 8 warps (4 row x 2
// col-half), no-max softmax, P via ex2.approx.f16x2, l via ones-mma,
// 3-stage K/V ring, ONE __syncthreads per tile.
#define APITCH 136
#define ATTN_SMEM ((64 + 6 * 128) * APITCH * 2)   // Q | K0 V0 K1 V1 K2 V2
#define ONES_H2 0x3C003C00u
#define MASK_NEG -30000.0f

__global__ __launch_bounds__(256, 1)
void attn_kernel(float* __restrict__ out)
{
    extern __shared__ half sm[];
    __shared__ float xl1[64];

    const int bid = blockIdx.x;
    const int s   = (bid < 148) ? bid : (403 - bid);
    const int qt  = 31 - (s >> 3);
    const int b   = s & 7;
    const int q0  = qt * 64;
    const int nkt = (qt >> 1) + 1;

    const int tid  = threadIdx.x;
    const int lane = tid & 31;
    const int w    = tid >> 5;
    const int wr   = w & 3;
    const int wc   = w >> 2;
    const int l15  = lane & 15;
    const int g    = lane >> 2;
    const int t0   = lane & 3;

    const uint32_t qBase  = smem_u32(sm);
    const uint32_t kvBase = qBase + 64 * APITCH * 2;
    const uint32_t TILEB  = 128 * APITCH * 2;

    const uint32_t qAddr = qBase + (((wr * 16 + l15) * APITCH) + (lane >> 4) * 8) * 2;
    uint32_t kOff[4];
    #pragma unroll
    for (int nbp = 0; nbp < 4; nbp++)
        kOff[nbp] = (((wc * 64 + nbp * 16 + (l15 & 7) + (lane >> 4) * 8) * APITCH)
                     + ((lane >> 3) & 1) * 8) * 2;
    const uint32_t vOff = (((wc * 64 + l15) * APITCH) + (lane >> 4) * 8) * 2;

    const half* Qg  = g_q + ((size_t)b * SEQ + q0) * HD;
    const half* Kgb = g_k + (size_t)b * SEQ * HD;
    const half* Vgb = g_v + (size_t)b * SEQ * HD;

    auto load_tile = [&](int st, int tile) {
        const uint32_t kB = kvBase + st * 2 * TILEB;
        #pragma unroll
        for (int i = 0; i < 8; i++) {
            int p = tid + 256 * i, row = p >> 4, c8 = p & 15;
            cp16(kB + (row * APITCH + c8 * 8) * 2,
                 Kgb + (size_t)(tile * 128 + row) * HD + c8 * 8);
            cp16(kB + TILEB + (row * APITCH + c8 * 8) * 2,
                 Vgb + (size_t)(tile * 128 + row) * HD + c8 * 8);
        }
    };

    #pragma unroll
    for (int i = 0; i < 4; i++) {
        int p = tid + 256 * i, row = p >> 4, c8 = p & 15;
        cp16(qBase + (row * APITCH + c8 * 8) * 2, Qg + row * HD + c8 * 8);
    }
    cp_commit();
    load_tile(0, 0);
    cp_commit();
    if (nkt > 1) load_tile(1, 1);
    cp_commit();

    cp_wait<1>();
    __syncthreads();

    uint32_t qa[8][4];
    #pragma unroll
    for (int ks = 0; ks < 8; ks++)
        ldsm_x4(qa[ks][0], qa[ks][1], qa[ks][2], qa[ks][3], qAddr + ks * 32);

    float O[16][4];
    #pragma unroll
    for (int i = 0; i < 16; i++)
        #pragma unroll
        for (int r = 0; r < 4; r++) O[i][r] = 0.f;
    float lrun0 = 0.f, lrun1 = 0.f;

    const int rl0 = wr * 16 + g;
    const int qr0 = q0 + rl0;

    for (int kt = 0; kt < nkt; kt++) {
        const int k0  = kt * 128;
        const int st  = kt % 3;
        const uint32_t kB = kvBase + st * 2 * TILEB;
        const uint32_t vB = kB + TILEB;

        if (kt > 0) {
            cp_wait<1>();
            __syncthreads();
        }

        float S[8][4];
        #pragma unroll
        for (int i = 0; i < 8; i++)
            #pragma unroll
            for (int r = 0; r < 4; r++) S[i][r] = 0.f;

        #pragma unroll
        for (int ks = 0; ks < 8; ks++) {
            #pragma unroll
            for (int nbp = 0; nbp < 4; nbp++) {
                uint32_t b0, b1, b2, b3;
                ldsm_x4(b0, b1, b2, b3, kB + kOff[nbp] + ks * 32);
                mma16816(S[2 * nbp],     qa[ks][0], qa[ks][1], qa[ks][2], qa[ks][3], b0, b1);
                mma16816(S[2 * nbp + 1], qa[ks][0], qa[ks][1], qa[ks][2], qa[ks][3], b2, b3);
            }
        }

        const bool need_mask = (kt == nkt - 1);
        uint32_t P[8][2];
        #pragma unroll
        for (int nb = 0; nb < 8; nb++) {
            if (need_mask) {
                int key = k0 + wc * 64 + nb * 8 + 2 * t0;
                if (key     > qr0)     S[nb][0] = MASK_NEG;
                if (key + 1 > qr0)     S[nb][1] = MASK_NEG;
                if (key     > qr0 + 8) S[nb][2] = MASK_NEG;
                if (key + 1 > qr0 + 8) S[nb][3] = MASK_NEG;
            }
            P[nb][0] = h2exp2(pack_h2(S[nb][0], S[nb][1]));
            P[nb][1] = h2exp2(pack_h2(S[nb][2], S[nb][3]));
        }

        float lacc[4] = {0.f, 0.f, 0.f, 0.f};
        #pragma unroll
        for (int ks2 = 0; ks2 < 4; ks2++) {
            uint32_t pa0 = P[2 * ks2][0],     pa1 = P[2 * ks2][1];
            uint32_t pa2 = P[2 * ks2 + 1][0], pa3 = P[2 * ks2 + 1][1];
            mma16816(lacc, pa0, pa1, pa2, pa3, ONES_H2, ONES_H2);
            #pragma unroll
            for (int dnbp = 0; dnbp < 8; dnbp++) {
                uint32_t b0, b1, b2, b3;
                ldsm_x4_t(b0, b1, b2, b3,
                          vB + vOff + (ks2 * 16 * APITCH + dnbp * 16) * 2);
                mma16816(O[2 * dnbp],     pa0, pa1, pa2, pa3, b0, b1);
                mma16816(O[2 * dnbp + 1], pa0, pa1, pa2, pa3, b2, b3);
            }
        }
        lrun0 += lacc[0];
        lrun1 += lacc[2];

        if (kt + 2 < nkt) load_tile((kt + 2) % 3, kt + 2);
        cp_commit();
    }

    __syncthreads();
    float* Ored = (float*)(sm + 64 * APITCH);
    if (wc == 1) {
        if (t0 == 0) { xl1[rl0] = lrun0; xl1[rl0 + 8] = lrun1; }
        #pragma unroll
        for (int dnb = 0; dnb < 16; dnb++) {
            int c = dnb * 8 + 2 * t0;
            *(float2*)&Ored[rl0 * 132 + c]       = make_float2(O[dnb][0], O[dnb][1]);
            *(float2*)&Ored[(rl0 + 8) * 132 + c] = make_float2(O[dnb][2], O[dnb][3]);
        }
    }
    __syncthreads();
    if (wc == 0) {
        const float invl0 = 1.0f / (lrun0 + xl1[rl0]);
        const float invl1 = 1.0f / (lrun1 + xl1[rl0 + 8]);
        #pragma unroll
        for (int dnb = 0; dnb < 16; dnb++) {
            int c = dnb * 8 + 2 * t0;
            float2 a0 = *(const float2*)&Ored[rl0 * 132 + c];
            float2 a1 = *(const float2*)&Ored[(rl0 + 8) * 132 + c];
            size_t r0 = ((size_t)b * SEQ + q0 + rl0) * HD + c;
            size_t r1 = r0 + 8 * HD;
            *(float2*)&out[r0] = make_float2((O[dnb][0] + a0.x) * invl0,
                                             (O[dnb][1] + a0.y) * invl0);
            *(float2*)&out[r1] = make_float2((O[dnb][2] + a1.x) * invl1,
                                             (O[dnb][3] + a1.y) * invl1);
        }
    }
}

// ----------------------------------------------------------------
extern "C" void kernel_launch(void* const* d_in, const int* in_sizes, int n_in,
                              void* d_out, int out_size)
{
    const float* x  = (const float*)d_in[0];
    const float* Wq = (const float*)d_in[1];
    const float* Wk = (const float*)d_in[2];
    const float* Wv = (const float*)d_in[3];
    float* out = (float*)d_out;

    cvt_w_kernel<<<384, 256>>>(Wq, Wk, Wv);

    cudaFuncSetAttribute(proj_kernel,
                         cudaFuncAttributeMaxDynamicSharedMemorySize, PROJ_SMEM);
    proj_kernel<<<dim3((BATCH * SEQ) / 128, 3), 256, PROJ_SMEM>>>(x);

    cudaFuncSetAttribute(attn_kernel,
                         cudaFuncAttributeMaxDynamicSharedMemorySize, ATTN_SMEM);
    attn_kernel<<<256, 256, ATTN_SMEM>>>(out);
}

// round 16
// speedup vs baseline: 1.1078x; 1.1078x over previous
#include <cuda_runtime.h>
#include <cuda_fp16.h>
#include <stdint.h>

#define BATCH 8
#define SEQ   2048
#define EMB   1024
#define HD    128

// fp16 copies of inputs (converted once per launch)
__device__ half g_x[BATCH * SEQ * EMB];   // 33.5MB
__device__ half g_w[3 * HD * EMB];        // Wq|Wk|Wv
// fp16 scratch for q,k,v
__device__ half g_q[BATCH * SEQ * HD];
__device__ half g_k[BATCH * SEQ * HD];
__device__ half g_v[BATCH * SEQ * HD];

// ---------------------------------------------------------------- helpers
__device__ __forceinline__ uint32_t smem_u32(const void* p) {
    uint32_t a;
    asm("{ .reg .u64 t; cvta.to.shared.u64 t, %1; cvt.u32.u64 %0, t; }"
        : "=r"(a) : "l"(p));
    return a;
}
__device__ __forceinline__ void ldsm_x4(uint32_t& r0, uint32_t& r1, uint32_t& r2,
                                        uint32_t& r3, uint32_t addr) {
    asm volatile("ldmatrix.sync.aligned.m8n8.x4.shared.b16 {%0,%1,%2,%3}, [%4];"
                 : "=r"(r0), "=r"(r1), "=r"(r2), "=r"(r3) : "r"(addr));
}
__device__ __forceinline__ void ldsm_x4_t(uint32_t& r0, uint32_t& r1, uint32_t& r2,
                                          uint32_t& r3, uint32_t addr) {
    asm volatile("ldmatrix.sync.aligned.m8n8.x4.trans.shared.b16 {%0,%1,%2,%3}, [%4];"
                 : "=r"(r0), "=r"(r1), "=r"(r2), "=r"(r3) : "r"(addr));
}
__device__ __forceinline__ void mma16816(float* c, uint32_t a0, uint32_t a1,
                                         uint32_t a2, uint32_t a3,
                                         uint32_t b0, uint32_t b1) {
    asm volatile(
        "mma.sync.aligned.m16n8k16.row.col.f32.f16.f16.f32 "
        "{%0,%1,%2,%3},{%4,%5,%6,%7},{%8,%9},{%0,%1,%2,%3};"
        : "+f"(c[0]), "+f"(c[1]), "+f"(c[2]), "+f"(c[3])
        : "r"(a0), "r"(a1), "r"(a2), "r"(a3), "r"(b0), "r"(b1));
}
__device__ __forceinline__ uint32_t pack_h2(float lo, float hi) {
    uint32_t r;
    asm("cvt.rn.f16x2.f32 %0, %1, %2;" : "=r"(r) : "f"(hi), "f"(lo));
    return r;
}
__device__ __forceinline__ uint32_t h2exp2(uint32_t x) {
    uint32_t r;
    asm("ex2.approx.f16x2 %0, %1;" : "=r"(r) : "r"(x));
    return r;
}
__device__ __forceinline__ void cp16(uint32_t dst, const void* src) {
    asm volatile("cp.async.cg.shared.global [%0], [%1], 16;"
                 :: "r"(dst), "l"(src));
}
__device__ __forceinline__ void cp_commit() {
    asm volatile("cp.async.commit_group;");
}
template <int N>
__device__ __forceinline__ void cp_wait() {
    asm volatile("cp.async.wait_group %0;" :: "n"(N));
}

// ---------------------------------------------------------------- converter
// X (16384 blk-equivalents) + W (384) in one kernel, 4 independent float4
// per thread (MLP=4) to saturate DRAM.
#define CVT_XBLKS 4096   // X handled by 4096 blocks, 4 float4/thread
__global__ __launch_bounds__(256)
void cvt_kernel(const float* __restrict__ X,
                const float* __restrict__ Wq,
                const float* __restrict__ Wk,
                const float* __restrict__ Wv)
{
    if (blockIdx.x < CVT_XBLKS) {
        // 4 independent float4 chunks, strided by 256 threads
        size_t base = (size_t)blockIdx.x * 1024 + threadIdx.x;
        float4 v0 = *(const float4*)(X + (base +   0) * 4);
        float4 v1 = *(const float4*)(X + (base + 256) * 4);
        float4 v2 = *(const float4*)(X + (base + 512) * 4);
        float4 v3 = *(const float4*)(X + (base + 768) * 4);
        *(uint2*)&g_x[(base +   0) * 4] = make_uint2(pack_h2(v0.x, v0.y), pack_h2(v0.z, v0.w));
        *(uint2*)&g_x[(base + 256) * 4] = make_uint2(pack_h2(v1.x, v1.y), pack_h2(v1.z, v1.w));
        *(uint2*)&g_x[(base + 512) * 4] = make_uint2(pack_h2(v2.x, v2.y), pack_h2(v2.z, v2.w));
        *(uint2*)&g_x[(base + 768) * 4] = make_uint2(pack_h2(v3.x, v3.y), pack_h2(v3.z, v3.w));
    } else {
        size_t i4 = (size_t)(blockIdx.x - CVT_XBLKS) * 256 + threadIdx.x;
        size_t j  = i4 * 4;
        const float* src = (j < 131072) ? Wq : (j < 262144) ? Wk : Wv;
        size_t off = j & 131071;
        float4 v = *(const float4*)(src + off);
        *(uint2*)&g_w[j] = make_uint2(pack_h2(v.x, v.y), pack_h2(v.z, v.w));
    }
}

// ---------------------------------------------------------------- projection
// R12 proj with earlier prefetch: load_stage(t+2) issued right after the
// barrier (stage (t+2)%3 last read at iter t-1 -> safe), overlapping both
// this iteration's mma AND the next. 128x128 CTA, 8 warps, 2 CTA/SM.
#define PP 72
#define PSTG (128 * PP)
#define PSTGB (PSTG * 2)
#define PROJ_SMEM (6 * PSTGB)

__global__ __launch_bounds__(256, 2)
void proj_kernel()
{
    extern __shared__ half psm[];
    const uint32_t base  = smem_u32(psm);
    const uint32_t bBase = base + 3 * PSTGB;

    half* outp = (blockIdx.y == 0) ? g_q : (blockIdx.y == 1) ? g_k : g_v;
    const half* Ab = g_x + (size_t)blockIdx.x * 128 * EMB;
    const half* Bb = g_w + (size_t)blockIdx.y * HD * EMB;

    const int tid  = threadIdx.x;
    const int lane = tid & 31;
    const int w    = tid >> 5;
    const int wm   = w >> 2;
    const int wn   = w & 3;
    const int l15  = lane & 15;
    const int g    = lane >> 2;
    const int t0   = lane & 3;

    float acc[4][4][4];
    #pragma unroll
    for (int i = 0; i < 4; i++)
        #pragma unroll
        for (int j = 0; j < 4; j++)
            #pragma unroll
            for (int r = 0; r < 4; r++) acc[i][j][r] = 0.f;

    uint32_t offA[4], offB[2];
    #pragma unroll
    for (int mb = 0; mb < 4; mb++)
        offA[mb] = (((wm * 64 + mb * 16 + l15) * PP) + (lane >> 4) * 8) * 2;
    #pragma unroll
    for (int nbp = 0; nbp < 2; nbp++)
        offB[nbp] = (((wn * 32 + nbp * 16 + (l15 & 7) + (lane >> 4) * 8) * PP)
                     + ((lane >> 3) & 1) * 8) * 2;

    auto load_stage = [&](int st, int t) {
        const int kt = t * 64;
        #pragma unroll
        for (int i = 0; i < 4; i++) {
            int p = tid + 256 * i, row = p >> 3, c = p & 7;
            cp16(base + st * PSTGB + (row * PP + c * 8) * 2,
                 Ab + (size_t)row * EMB + kt + c * 8);
            cp16(bBase + st * PSTGB + (row * PP + c * 8) * 2,
                 Bb + (size_t)row * EMB + kt + c * 8);
        }
    };

    load_stage(0, 0); cp_commit();
    load_stage(1, 1); cp_commit();

    #pragma unroll 2
    for (int t = 0; t < 16; t++) {
        const int cur = t % 3;
        cp_wait<1>();
        __syncthreads();

        // prefetch EARLY: slot (t+2)%3 was last read at iter t-1, which all
        // warps finished before the barrier above.
        if (t + 2 < 16) load_stage((t + 2) % 3, t + 2);
        cp_commit();

        const uint32_t aB = base + cur * PSTGB;
        const uint32_t bB = bBase + cur * PSTGB;
        #pragma unroll
        for (int ks = 0; ks < 4; ks++) {
            uint32_t a[4][4];
            #pragma unroll
            for (int mb = 0; mb < 4; mb++)
                ldsm_x4(a[mb][0], a[mb][1], a[mb][2], a[mb][3],
                        aB + offA[mb] + ks * 32);
            #pragma unroll
            for (int nbp = 0; nbp < 2; nbp++) {
                uint32_t b0, b1, b2, b3;
                ldsm_x4(b0, b1, b2, b3, bB + offB[nbp] + ks * 32);
                #pragma unroll
                for (int mb = 0; mb < 4; mb++) {
                    mma16816(acc[mb][2 * nbp],     a[mb][0], a[mb][1], a[mb][2], a[mb][3], b0, b1);
                    mma16816(acc[mb][2 * nbp + 1], a[mb][0], a[mb][1], a[mb][2], a[mb][3], b2, b3);
                }
            }
        }
    }

    const float qs = (blockIdx.y == 0) ? 0.011271055007086637f : 1.0f;
    const int m0 = blockIdx.x * 128;
    #pragma unroll
    for (int mb = 0; mb < 4; mb++)
        #pragma unroll
        for (int nb = 0; nb < 4; nb++) {
            int row = m0 + wm * 64 + mb * 16 + g;
            int col = wn * 32 + nb * 8 + 2 * t0;
            *(uint32_t*)&outp[(size_t)row * HD + col] =
                pack_h2(acc[mb][nb][0] * qs, acc[mb][nb][1] * qs);
            *(uint32_t*)&outp[(size_t)(row + 8) * HD + col] =
                pack_h2(acc[mb][nb][2] * qs, acc[mb][nb][3] * qs);
        }
}

// ---------------------------------------------------------------- attention
// R12 attention with earlier prefetch issue (same safety argument).
#define APITCH 136
#define ATTN_SMEM ((64 + 6 * 128) * APITCH * 2)   // Q | K0 V0 K1 V1 K2 V2
#define ONES_H2 0x3C003C00u
#define MASK_NEG -30000.0f

__global__ __launch_bounds__(256, 1)
void attn_kernel(float* __restrict__ out)
{
    extern __shared__ half sm[];
    __shared__ float xl1[64];

    const int bid = blockIdx.x;
    const int s   = (bid < 148) ? bid : (403 - bid);
    const int qt  = 31 - (s >> 3);
    const int b   = s & 7;
    const int q0  = qt * 64;
    const int nkt = (qt >> 1) + 1;

    const int tid  = threadIdx.x;
    const int lane = tid & 31;
    const int w    = tid >> 5;
    const int wr   = w & 3;
    const int wc   = w >> 2;
    const int l15  = lane & 15;
    const int g    = lane >> 2;
    const int t0   = lane & 3;

    const uint32_t qBase  = smem_u32(sm);
    const uint32_t kvBase = qBase + 64 * APITCH * 2;
    const uint32_t TILEB  = 128 * APITCH * 2;

    const uint32_t qAddr = qBase + (((wr * 16 + l15) * APITCH) + (lane >> 4) * 8) * 2;
    uint32_t kOff[4];
    #pragma unroll
    for (int nbp = 0; nbp < 4; nbp++)
        kOff[nbp] = (((wc * 64 + nbp * 16 + (l15 & 7) + (lane >> 4) * 8) * APITCH)
                     + ((lane >> 3) & 1) * 8) * 2;
    const uint32_t vOff = (((wc * 64 + l15) * APITCH) + (lane >> 4) * 8) * 2;

    const half* Qg  = g_q + ((size_t)b * SEQ + q0) * HD;
    const half* Kgb = g_k + (size_t)b * SEQ * HD;
    const half* Vgb = g_v + (size_t)b * SEQ * HD;

    auto load_tile = [&](int st, int tile) {
        const uint32_t kB = kvBase + st * 2 * TILEB;
        #pragma unroll
        for (int i = 0; i < 8; i++) {
            int p = tid + 256 * i, row = p >> 4, c8 = p & 15;
            cp16(kB + (row * APITCH + c8 * 8) * 2,
                 Kgb + (size_t)(tile * 128 + row) * HD + c8 * 8);
            cp16(kB + TILEB + (row * APITCH + c8 * 8) * 2,
                 Vgb + (size_t)(tile * 128 + row) * HD + c8 * 8);
        }
    };

    #pragma unroll
    for (int i = 0; i < 4; i++) {
        int p = tid + 256 * i, row = p >> 4, c8 = p & 15;
        cp16(qBase + (row * APITCH + c8 * 8) * 2, Qg + row * HD + c8 * 8);
    }
    cp_commit();
    load_tile(0, 0);
    cp_commit();
    if (nkt > 1) load_tile(1, 1);
    cp_commit();

    cp_wait<1>();
    __syncthreads();

    uint32_t qa[8][4];
    #pragma unroll
    for (int ks = 0; ks < 8; ks++)
        ldsm_x4(qa[ks][0], qa[ks][1], qa[ks][2], qa[ks][3], qAddr + ks * 32);

    float O[16][4];
    #pragma unroll
    for (int i = 0; i < 16; i++)
        #pragma unroll
        for (int r = 0; r < 4; r++) O[i][r] = 0.f;
    float lrun0 = 0.f, lrun1 = 0.f;

    const int rl0 = wr * 16 + g;
    const int qr0 = q0 + rl0;

    for (int kt = 0; kt < nkt; kt++) {
        const int k0  = kt * 128;
        const int st  = kt % 3;
        const uint32_t kB = kvBase + st * 2 * TILEB;
        const uint32_t vB = kB + TILEB;

        if (kt > 0) {
            cp_wait<1>();
            __syncthreads();
        }

        // prefetch EARLY: stage (kt+2)%3 last read at tile kt-1; all warps
        // finished it before the barrier above (prologue barrier for kt=0).
        if (kt + 2 < nkt) load_tile((kt + 2) % 3, kt + 2);
        cp_commit();

        float S[8][4];
        #pragma unroll
        for (int i = 0; i < 8; i++)
            #pragma unroll
            for (int r = 0; r < 4; r++) S[i][r] = 0.f;

        #pragma unroll
        for (int ks = 0; ks < 8; ks++) {
            #pragma unroll
            for (int nbp = 0; nbp < 4; nbp++) {
                uint32_t b0, b1, b2, b3;
                ldsm_x4(b0, b1, b2, b3, kB + kOff[nbp] + ks * 32);
                mma16816(S[2 * nbp],     qa[ks][0], qa[ks][1], qa[ks][2], qa[ks][3], b0, b1);
                mma16816(S[2 * nbp + 1], qa[ks][0], qa[ks][1], qa[ks][2], qa[ks][3], b2, b3);
            }
        }

        const bool need_mask = (kt == nkt - 1);
        uint32_t P[8][2];
        #pragma unroll
        for (int nb = 0; nb < 8; nb++) {
            if (need_mask) {
                int key = k0 + wc * 64 + nb * 8 + 2 * t0;
                if (key     > qr0)     S[nb][0] = MASK_NEG;
                if (key + 1 > qr0)     S[nb][1] = MASK_NEG;
                if (key     > qr0 + 8) S[nb][2] = MASK_NEG;
                if (key + 1 > qr0 + 8) S[nb][3] = MASK_NEG;
            }
            P[nb][0] = h2exp2(pack_h2(S[nb][0], S[nb][1]));
            P[nb][1] = h2exp2(pack_h2(S[nb][2], S[nb][3]));
        }

        float lacc[4] = {0.f, 0.f, 0.f, 0.f};
        #pragma unroll
        for (int ks2 = 0; ks2 < 4; ks2++) {
            uint32_t pa0 = P[2 * ks2][0],     pa1 = P[2 * ks2][1];
            uint32_t pa2 = P[2 * ks2 + 1][0], pa3 = P[2 * ks2 + 1][1];
            mma16816(lacc, pa0, pa1, pa2, pa3, ONES_H2, ONES_H2);
            #pragma unroll
            for (int dnbp = 0; dnbp < 8; dnbp++) {
                uint32_t b0, b1, b2, b3;
                ldsm_x4_t(b0, b1, b2, b3,
                          vB + vOff + (ks2 * 16 * APITCH + dnbp * 16) * 2);
                mma16816(O[2 * dnbp],     pa0, pa1, pa2, pa3, b0, b1);
                mma16816(O[2 * dnbp + 1], pa0, pa1, pa2, pa3, b2, b3);
            }
        }
        lrun0 += lacc[0];
        lrun1 += lacc[2];
    }

    __syncthreads();
    float* Ored = (float*)(sm + 64 * APITCH);
    if (wc == 1) {
        if (t0 == 0) { xl1[rl0] = lrun0; xl1[rl0 + 8] = lrun1; }
        #pragma unroll
        for (int dnb = 0; dnb < 16; dnb++) {
            int c = dnb * 8 + 2 * t0;
            *(float2*)&Ored[rl0 * 132 + c]       = make_float2(O[dnb][0], O[dnb][1]);
            *(float2*)&Ored[(rl0 + 8) * 132 + c] = make_float2(O[dnb][2], O[dnb][3]);
        }
    }
    __syncthreads();
    if (wc == 0) {
        const float invl0 = 1.0f / (lrun0 + xl1[rl0]);
        const float invl1 = 1.0f / (lrun1 + xl1[rl0 + 8]);
        #pragma unroll
        for (int dnb = 0; dnb < 16; dnb++) {
            int c = dnb * 8 + 2 * t0;
            float2 a0 = *(const float2*)&Ored[rl0 * 132 + c];
            float2 a1 = *(const float2*)&Ored[(rl0 + 8) * 132 + c];
            size_t r0 = ((size_t)b * SEQ + q0 + rl0) * HD + c;
            size_t r1 = r0 + 8 * HD;
            *(float2*)&out[r0] = make_float2((O[dnb][0] + a0.x) * invl0,
                                             (O[dnb][1] + a0.y) * invl0);
            *(float2*)&out[r1] = make_float2((O[dnb][2] + a1.x) * invl1,
                                             (O[dnb][3] + a1.y) * invl1);
        }
    }
}

// ----------------------------------------------------------------
extern "C" void kernel_launch(void* const* d_in, const int* in_sizes, int n_in,
                              void* d_out, int out_size)
{
    const float* x  = (const float*)d_in[0];
    const float* Wq = (const float*)d_in[1];
    const float* Wk = (const float*)d_in[2];
    const float* Wv = (const float*)d_in[3];
    float* out = (float*)d_out;

    cvt_kernel<<<CVT_XBLKS + 384, 256>>>(x, Wq, Wk, Wv);

    cudaFuncSetAttribute(proj_kernel,
                         cudaFuncAttributeMaxDynamicSharedMemorySize, PROJ_SMEM);
    proj_kernel<<<dim3((BATCH * SEQ) / 128, 3), 256, PROJ_SMEM>>>();

    cudaFuncSetAttribute(attn_kernel,
                         cudaFuncAttributeMaxDynamicSharedMemorySize, ATTN_SMEM);
    attn_kernel<<<256, 256, ATTN_SMEM>>>(out);
}

// round 17
// speedup vs baseline: 1.1692x; 1.0553x over previous
#include <cuda_runtime.h>
#include <cuda_fp16.h>
#include <stdint.h>

#define BATCH 8
#define SEQ   2048
#define EMB   1024
#define HD    128

// fp16 copies of inputs (converted once per launch)
__device__ half g_x[BATCH * SEQ * EMB];   // 33.5MB
__device__ half g_w[3 * HD * EMB];        // Wq|Wk|Wv
// fp16 scratch for q,k,v
__device__ half g_q[BATCH * SEQ * HD];
__device__ half g_k[BATCH * SEQ * HD];
__device__ half g_v[BATCH * SEQ * HD];

// ---------------------------------------------------------------- helpers
__device__ __forceinline__ uint32_t smem_u32(const void* p) {
    uint32_t a;
    asm("{ .reg .u64 t; cvta.to.shared.u64 t, %1; cvt.u32.u64 %0, t; }"
        : "=r"(a) : "l"(p));
    return a;
}
__device__ __forceinline__ void ldsm_x4(uint32_t& r0, uint32_t& r1, uint32_t& r2,
                                        uint32_t& r3, uint32_t addr) {
    asm volatile("ldmatrix.sync.aligned.m8n8.x4.shared.b16 {%0,%1,%2,%3}, [%4];"
                 : "=r"(r0), "=r"(r1), "=r"(r2), "=r"(r3) : "r"(addr));
}
__device__ __forceinline__ void ldsm_x4_t(uint32_t& r0, uint32_t& r1, uint32_t& r2,
                                          uint32_t& r3, uint32_t addr) {
    asm volatile("ldmatrix.sync.aligned.m8n8.x4.trans.shared.b16 {%0,%1,%2,%3}, [%4];"
                 : "=r"(r0), "=r"(r1), "=r"(r2), "=r"(r3) : "r"(addr));
}
__device__ __forceinline__ void mma16816(float* c, uint32_t a0, uint32_t a1,
                                         uint32_t a2, uint32_t a3,
                                         uint32_t b0, uint32_t b1) {
    asm volatile(
        "mma.sync.aligned.m16n8k16.row.col.f32.f16.f16.f32 "
        "{%0,%1,%2,%3},{%4,%5,%6,%7},{%8,%9},{%0,%1,%2,%3};"
        : "+f"(c[0]), "+f"(c[1]), "+f"(c[2]), "+f"(c[3])
        : "r"(a0), "r"(a1), "r"(a2), "r"(a3), "r"(b0), "r"(b1));
}
__device__ __forceinline__ uint32_t pack_h2(float lo, float hi) {
    uint32_t r;
    asm("cvt.rn.f16x2.f32 %0, %1, %2;" : "=r"(r) : "f"(hi), "f"(lo));
    return r;
}
__device__ __forceinline__ uint32_t h2exp2(uint32_t x) {
    uint32_t r;
    asm("ex2.approx.f16x2 %0, %1;" : "=r"(r) : "r"(x));
    return r;
}
__device__ __forceinline__ void cp16(uint32_t dst, const void* src) {
    asm volatile("cp.async.cg.shared.global [%0], [%1], 16;"
                 :: "r"(dst), "l"(src));
}
__device__ __forceinline__ void cp_commit() {
    asm volatile("cp.async.commit_group;");
}
template <int N>
__device__ __forceinline__ void cp_wait() {
    asm volatile("cp.async.wait_group %0;" :: "n"(N));
}

// ---------------------------------------------------------------- converter
// X + W in one kernel. X path: 8 independent float4 round-trips per thread
// (MLP=8) to saturate DRAM.
#define CVT_XBLKS 2048   // X handled by 2048 blocks, 8 float4/thread
__global__ __launch_bounds__(256)
void cvt_kernel(const float* __restrict__ X,
                const float* __restrict__ Wq,
                const float* __restrict__ Wk,
                const float* __restrict__ Wv)
{
    if (blockIdx.x < CVT_XBLKS) {
        size_t base = (size_t)blockIdx.x * 2048 + threadIdx.x;
        float4 v[8];
        #pragma unroll
        for (int i = 0; i < 8; i++)
            v[i] = *(const float4*)(X + (base + 256 * i) * 4);
        #pragma unroll
        for (int i = 0; i < 8; i++)
            *(uint2*)&g_x[(base + 256 * i) * 4] =
                make_uint2(pack_h2(v[i].x, v[i].y), pack_h2(v[i].z, v[i].w));
    } else {
        size_t i4 = (size_t)(blockIdx.x - CVT_XBLKS) * 256 + threadIdx.x;
        size_t j  = i4 * 4;
        const float* src = (j < 131072) ? Wq : (j < 262144) ? Wk : Wv;
        size_t off = j & 131071;
        float4 v = *(const float4*)(src + off);
        *(uint2*)&g_w[j] = make_uint2(pack_h2(v.x, v.y), pack_h2(v.z, v.w));
    }
}

// ---------------------------------------------------------------- projection
// R12 proj (verbatim): fp16 via cp.async, k-stage 64, 3-stage ring, ONE
// __syncthreads per stage, prefetch issued AFTER the mma block.
#define PP 72
#define PSTG (128 * PP)
#define PSTGB (PSTG * 2)
#define PROJ_SMEM (6 * PSTGB)

__global__ __launch_bounds__(256, 2)
void proj_kernel()
{
    extern __shared__ half psm[];
    const uint32_t base  = smem_u32(psm);
    const uint32_t bBase = base + 3 * PSTGB;

    half* outp = (blockIdx.y == 0) ? g_q : (blockIdx.y == 1) ? g_k : g_v;
    const half* Ab = g_x + (size_t)blockIdx.x * 128 * EMB;
    const half* Bb = g_w + (size_t)blockIdx.y * HD * EMB;

    const int tid  = threadIdx.x;
    const int lane = tid & 31;
    const int w    = tid >> 5;
    const int wm   = w >> 2;
    const int wn   = w & 3;
    const int l15  = lane & 15;
    const int g    = lane >> 2;
    const int t0   = lane & 3;

    float acc[4][4][4];
    #pragma unroll
    for (int i = 0; i < 4; i++)
        #pragma unroll
        for (int j = 0; j < 4; j++)
            #pragma unroll
            for (int r = 0; r < 4; r++) acc[i][j][r] = 0.f;

    uint32_t offA[4], offB[2];
    #pragma unroll
    for (int mb = 0; mb < 4; mb++)
        offA[mb] = (((wm * 64 + mb * 16 + l15) * PP) + (lane >> 4) * 8) * 2;
    #pragma unroll
    for (int nbp = 0; nbp < 2; nbp++)
        offB[nbp] = (((wn * 32 + nbp * 16 + (l15 & 7) + (lane >> 4) * 8) * PP)
                     + ((lane >> 3) & 1) * 8) * 2;

    auto load_stage = [&](int st, int t) {
        const int kt = t * 64;
        #pragma unroll
        for (int i = 0; i < 4; i++) {
            int p = tid + 256 * i, row = p >> 3, c = p & 7;
            cp16(base + st * PSTGB + (row * PP + c * 8) * 2,
                 Ab + (size_t)row * EMB + kt + c * 8);
            cp16(bBase + st * PSTGB + (row * PP + c * 8) * 2,
                 Bb + (size_t)row * EMB + kt + c * 8);
        }
    };

    load_stage(0, 0); cp_commit();
    load_stage(1, 1); cp_commit();

    #pragma unroll 2
    for (int t = 0; t < 16; t++) {
        const int cur = t % 3;
        cp_wait<1>();
        __syncthreads();

        const uint32_t aB = base + cur * PSTGB;
        const uint32_t bB = bBase + cur * PSTGB;
        #pragma unroll
        for (int ks = 0; ks < 4; ks++) {
            uint32_t a[4][4];
            #pragma unroll
            for (int mb = 0; mb < 4; mb++)
                ldsm_x4(a[mb][0], a[mb][1], a[mb][2], a[mb][3],
                        aB + offA[mb] + ks * 32);
            #pragma unroll
            for (int nbp = 0; nbp < 2; nbp++) {
                uint32_t b0, b1, b2, b3;
                ldsm_x4(b0, b1, b2, b3, bB + offB[nbp] + ks * 32);
                #pragma unroll
                for (int mb = 0; mb < 4; mb++) {
                    mma16816(acc[mb][2 * nbp],     a[mb][0], a[mb][1], a[mb][2], a[mb][3], b0, b1);
                    mma16816(acc[mb][2 * nbp + 1], a[mb][0], a[mb][1], a[mb][2], a[mb][3], b2, b3);
                }
            }
        }
        if (t + 2 < 16) load_stage((t + 2) % 3, t + 2);
        cp_commit();
    }

    const float qs = (blockIdx.y == 0) ? 0.011271055007086637f : 1.0f;
    const int m0 = blockIdx.x * 128;
    #pragma unroll
    for (int mb = 0; mb < 4; mb++)
        #pragma unroll
        for (int nb = 0; nb < 4; nb++) {
            int row = m0 + wm * 64 + mb * 16 + g;
            int col = wn * 32 + nb * 8 + 2 * t0;
            *(uint32_t*)&outp[(size_t)row * HD + col] =
                pack_h2(acc[mb][nb][0] * qs, acc[mb][nb][1] * qs);
            *(uint32_t*)&outp[(size_t)(row + 8) * HD + col] =
                pack_h2(acc[mb][nb][2] * qs, acc[mb][nb][3] * qs);
        }
}

// ---------------------------------------------------------------- attention
// R12 attention (verbatim): BR=64, BC=128, 8 warps (4 row x 2 col-half),
// no-max softmax, P via ex2.approx.f16x2, l via ones-mma, 3-stage K/V ring,
// ONE __syncthreads per tile, prefetch AFTER the mma block.
#define APITCH 136
#define ATTN_SMEM ((64 + 6 * 128) * APITCH * 2)   // Q | K0 V0 K1 V1 K2 V2
#define ONES_H2 0x3C003C00u
#define MASK_NEG -30000.0f

__global__ __launch_bounds__(256, 1)
void attn_kernel(float* __restrict__ out)
{
    extern __shared__ half sm[];
    __shared__ float xl1[64];

    const int bid = blockIdx.x;
    const int s   = (bid < 148) ? bid : (403 - bid);
    const int qt  = 31 - (s >> 3);
    const int b   = s & 7;
    const int q0  = qt * 64;
    const int nkt = (qt >> 1) + 1;

    const int tid  = threadIdx.x;
    const int lane = tid & 31;
    const int w    = tid >> 5;
    const int wr   = w & 3;
    const int wc   = w >> 2;
    const int l15  = lane & 15;
    const int g    = lane >> 2;
    const int t0   = lane & 3;

    const uint32_t qBase  = smem_u32(sm);
    const uint32_t kvBase = qBase + 64 * APITCH * 2;
    const uint32_t TILEB  = 128 * APITCH * 2;

    const uint32_t qAddr = qBase + (((wr * 16 + l15) * APITCH) + (lane >> 4) * 8) * 2;
    uint32_t kOff[4];
    #pragma unroll
    for (int nbp = 0; nbp < 4; nbp++)
        kOff[nbp] = (((wc * 64 + nbp * 16 + (l15 & 7) + (lane >> 4) * 8) * APITCH)
                     + ((lane >> 3) & 1) * 8) * 2;
    const uint32_t vOff = (((wc * 64 + l15) * APITCH) + (lane >> 4) * 8) * 2;

    const half* Qg  = g_q + ((size_t)b * SEQ + q0) * HD;
    const half* Kgb = g_k + (size_t)b * SEQ * HD;
    const half* Vgb = g_v + (size_t)b * SEQ * HD;

    auto load_tile = [&](int st, int tile) {
        const uint32_t kB = kvBase + st * 2 * TILEB;
        #pragma unroll
        for (int i = 0; i < 8; i++) {
            int p = tid + 256 * i, row = p >> 4, c8 = p & 15;
            cp16(kB + (row * APITCH + c8 * 8) * 2,
                 Kgb + (size_t)(tile * 128 + row) * HD + c8 * 8);
            cp16(kB + TILEB + (row * APITCH + c8 * 8) * 2,
                 Vgb + (size_t)(tile * 128 + row) * HD + c8 * 8);
        }
    };

    #pragma unroll
    for (int i = 0; i < 4; i++) {
        int p = tid + 256 * i, row = p >> 4, c8 = p & 15;
        cp16(qBase + (row * APITCH + c8 * 8) * 2, Qg + row * HD + c8 * 8);
    }
    cp_commit();
    load_tile(0, 0);
    cp_commit();
    if (nkt > 1) load_tile(1, 1);
    cp_commit();

    cp_wait<1>();
    __syncthreads();

    uint32_t qa[8][4];
    #pragma unroll
    for (int ks = 0; ks < 8; ks++)
        ldsm_x4(qa[ks][0], qa[ks][1], qa[ks][2], qa[ks][3], qAddr + ks * 32);

    float O[16][4];
    #pragma unroll
    for (int i = 0; i < 16; i++)
        #pragma unroll
        for (int r = 0; r < 4; r++) O[i][r] = 0.f;
    float lrun0 = 0.f, lrun1 = 0.f;

    const int rl0 = wr * 16 + g;
    const int qr0 = q0 + rl0;

    for (int kt = 0; kt < nkt; kt++) {
        const int k0  = kt * 128;
        const int st  = kt % 3;
        const uint32_t kB = kvBase + st * 2 * TILEB;
        const uint32_t vB = kB + TILEB;

        if (kt > 0) {
            cp_wait<1>();
            __syncthreads();
        }

        float S[8][4];
        #pragma unroll
        for (int i = 0; i < 8; i++)
            #pragma unroll
            for (int r = 0; r < 4; r++) S[i][r] = 0.f;

        #pragma unroll
        for (int ks = 0; ks < 8; ks++) {
            #pragma unroll
            for (int nbp = 0; nbp < 4; nbp++) {
                uint32_t b0, b1, b2, b3;
                ldsm_x4(b0, b1, b2, b3, kB + kOff[nbp] + ks * 32);
                mma16816(S[2 * nbp],     qa[ks][0], qa[ks][1], qa[ks][2], qa[ks][3], b0, b1);
                mma16816(S[2 * nbp + 1], qa[ks][0], qa[ks][1], qa[ks][2], qa[ks][3], b2, b3);
            }
        }

        const bool need_mask = (kt == nkt - 1);
        uint32_t P[8][2];
        #pragma unroll
        for (int nb = 0; nb < 8; nb++) {
            if (need_mask) {
                int key = k0 + wc * 64 + nb * 8 + 2 * t0;
                if (key     > qr0)     S[nb][0] = MASK_NEG;
                if (key + 1 > qr0)     S[nb][1] = MASK_NEG;
                if (key     > qr0 + 8) S[nb][2] = MASK_NEG;
                if (key + 1 > qr0 + 8) S[nb][3] = MASK_NEG;
            }
            P[nb][0] = h2exp2(pack_h2(S[nb][0], S[nb][1]));
            P[nb][1] = h2exp2(pack_h2(S[nb][2], S[nb][3]));
        }

        float lacc[4] = {0.f, 0.f, 0.f, 0.f};
        #pragma unroll
        for (int ks2 = 0; ks2 < 4; ks2++) {
            uint32_t pa0 = P[2 * ks2][0],     pa1 = P[2 * ks2][1];
            uint32_t pa2 = P[2 * ks2 + 1][0], pa3 = P[2 * ks2 + 1][1];
            mma16816(lacc, pa0, pa1, pa2, pa3, ONES_H2, ONES_H2);
            #pragma unroll
            for (int dnbp = 0; dnbp < 8; dnbp++) {
                uint32_t b0, b1, b2, b3;
                ldsm_x4_t(b0, b1, b2, b3,
                          vB + vOff + (ks2 * 16 * APITCH + dnbp * 16) * 2);
                mma16816(O[2 * dnbp],     pa0, pa1, pa2, pa3, b0, b1);
                mma16816(O[2 * dnbp + 1], pa0, pa1, pa2, pa3, b2, b3);
            }
        }
        lrun0 += lacc[0];
        lrun1 += lacc[2];

        if (kt + 2 < nkt) load_tile((kt + 2) % 3, kt + 2);
        cp_commit();
    }

    __syncthreads();
    float* Ored = (float*)(sm + 64 * APITCH);
    if (wc == 1) {
        if (t0 == 0) { xl1[rl0] = lrun0; xl1[rl0 + 8] = lrun1; }
        #pragma unroll
        for (int dnb = 0; dnb < 16; dnb++) {
            int c = dnb * 8 + 2 * t0;
            *(float2*)&Ored[rl0 * 132 + c]       = make_float2(O[dnb][0], O[dnb][1]);
            *(float2*)&Ored[(rl0 + 8) * 132 + c] = make_float2(O[dnb][2], O[dnb][3]);
        }
    }
    __syncthreads();
    if (wc == 0) {
        const float invl0 = 1.0f / (lrun0 + xl1[rl0]);
        const float invl1 = 1.0f / (lrun1 + xl1[rl0 + 8]);
        #pragma unroll
        for (int dnb = 0; dnb < 16; dnb++) {
            int c = dnb * 8 + 2 * t0;
            float2 a0 = *(const float2*)&Ored[rl0 * 132 + c];
            float2 a1 = *(const float2*)&Ored[(rl0 + 8) * 132 + c];
            size_t r0 = ((size_t)b * SEQ + q0 + rl0) * HD + c;
            size_t r1 = r0 + 8 * HD;
            *(float2*)&out[r0] = make_float2((O[dnb][0] + a0.x) * invl0,
                                             (O[dnb][1] + a0.y) * invl0);
            *(float2*)&out[r1] = make_float2((O[dnb][2] + a1.x) * invl1,
                                             (O[dnb][3] + a1.y) * invl1);
        }
    }
}

// ----------------------------------------------------------------
extern "C" void kernel_launch(void* const* d_in, const int* in_sizes, int n_in,
                              void* d_out, int out_size)
{
    const float* x  = (const float*)d_in[0];
    const float* Wq = (const float*)d_in[1];
    const float* Wk = (const float*)d_in[2];
    const float* Wv = (const float*)d_in[3];
    float* out = (float*)d_out;

    cvt_kernel<<<CVT_XBLKS + 384, 256>>>(x, Wq, Wk, Wv);

    cudaFuncSetAttribute(proj_kernel,
                         cudaFuncAttributeMaxDynamicSharedMemorySize, PROJ_SMEM);
    proj_kernel<<<dim3((BATCH * SEQ) / 128, 3), 256, PROJ_SMEM>>>();

    cudaFuncSetAttribute(attn_kernel,
                         cudaFuncAttributeMaxDynamicSharedMemorySize, ATTN_SMEM);
    attn_kernel<<<256, 256, ATTN_SMEM>>>(out);
}